// round 16
// baseline (speedup 1.0000x reference)
#include <cuda_runtime.h>
#include <cuda_bf16.h>
#include <math.h>
#include <stdint.h>

#define BN 512
#define VV 50000
#define KK 200
#define HH 300
#define HIDD 800
#define VP 50048
#define KP 256
#define HP 320
#define NH 896
#define Z1 16
#define Z2 32
#define NKT64 (VP/64)          // 782 k64-tiles over vocab
#define MT ((VV+127)/128)      // 391
#define NT64 (VP/64)           // 782 n-tiles for mm34
#define NP2 (NT64*4)

// ---------------- scratch ----------------
__device__ __align__(16) __nv_bfloat16 g_bows16[(size_t)BN*VP];
__device__ __align__(16) __nv_bfloat16 g_w1t[(size_t)NH*VP];
__device__ __align__(16) __nv_bfloat16 g_rho16[(size_t)VV*HP];
__device__ __align__(16) __nv_bfloat16 g_al16[(size_t)KP*HP];
__device__ __align__(16) __nv_bfloat16 g_dis16[(size_t)VV*KP];
__device__ __align__(16) __nv_bfloat16 g_disT16[(size_t)KP*VP];
__device__ __align__(16) __nv_bfloat16 g_tn16[(size_t)BN*KP];
__device__ __align__(16) __nv_bfloat16 g_th216[(size_t)BN*KP];
__device__ float g_p1[(size_t)Z1*BN*NH];
__device__ float g_p2[(size_t)Z2*BN*KP];
__device__ float g_hid[BN*HIDD];
__device__ float g_theta[BN*KK];
__device__ float g_tn[BN*KK];
__device__ float g_ntok[BN];
__device__ float g_invn[BN];
__device__ float g_S[KP];
__device__ float g_Sp[MT*KP];
__device__ float g_pF[NP2];
__device__ float g_pT[NP2];
__device__ float g_pB[BN];

// ---------------- helpers ----------------
__device__ __forceinline__ uint32_t s2u(const void* p) {
    uint32_t a;
    asm("{ .reg .u64 t; cvta.to.shared.u64 t, %1; cvt.u32.u64 %0, t; }" : "=r"(a) : "l"(p));
    return a;
}
__device__ __forceinline__ void cpa(uint32_t sa, const void* ga, int sz) {
    asm volatile("cp.async.cg.shared.global [%0], [%1], 16, %2;"
                 :: "r"(sa), "l"(ga), "r"(sz) : "memory");
}
#define CPCOMMIT() asm volatile("cp.async.commit_group;" ::: "memory")
#define CPWAIT(n)  asm volatile("cp.async.wait_group %0;" :: "n"(n) : "memory")
#define LDSM4(r, a) \
    asm volatile("ldmatrix.sync.aligned.m8n8.x4.shared.b16 {%0,%1,%2,%3}, [%4];" \
        : "=r"((r)[0]), "=r"((r)[1]), "=r"((r)[2]), "=r"((r)[3]) : "r"(a))

__device__ __forceinline__ void mma16816(float* c, const uint32_t* a, uint32_t b0, uint32_t b1) {
    asm volatile("mma.sync.aligned.m16n8k16.row.col.f32.bf16.bf16.f32 "
        "{%0,%1,%2,%3}, {%4,%5,%6,%7}, {%8,%9}, {%0,%1,%2,%3};"
        : "+f"(c[0]), "+f"(c[1]), "+f"(c[2]), "+f"(c[3])
        : "r"(a[0]), "r"(a[1]), "r"(a[2]), "r"(a[3]), "r"(b0), "r"(b1));
}
__device__ __forceinline__ void unp2(uint32_t u, float& a, float& b) {
    __nv_bfloat162 t = *reinterpret_cast<__nv_bfloat162*>(&u);
    a = __bfloat162float(t.x); b = __bfloat162float(t.y);
}
__device__ __forceinline__ uint32_t pk2(float a, float b) {
    return ((uint32_t)__bfloat16_as_ushort(__float2bfloat16_rn(b)) << 16) |
            (uint32_t)__bfloat16_as_ushort(__float2bfloat16_rn(a));
}

// mm template: K-tile 64, pitch 144
#define P64 144
#define T64B (128*P64)
#define STG64 (2*T64B)
#define MMS (3*STG64)

// mm34: K-tile 32, pitch 80 (2-stage)
#define PITCH 80
#define STG34 25600

// ---------------- bf16 HMMA GEMM template (K64, 3-stage) ----------------
template<int EPI>
__global__ void __launch_bounds__(256) mm() {
    extern __shared__ __align__(16) char smem[];
    const uint32_t sb = s2u(smem);
    const int tid = threadIdx.x, lane = tid & 31, wid = tid >> 5;
    const int wm = (wid & 3) * 32, wn = (wid >> 2) * 64;
    const int m0 = blockIdx.x * 128, n0 = blockIdx.y * 128;

    const __nv_bfloat16 *A, *B;
    int lda, ldb, kt0, ktn;
    bool azf = false;
    if (EPI == 0) { A = g_rho16; B = g_al16; lda = HP; ldb = HP; kt0 = 0; ktn = HP/64; azf = true; }
    else if (EPI == 1) { A = g_bows16; B = g_w1t; lda = VP; ldb = VP;
                         kt0 = blockIdx.z * 49; ktn = min(kt0 + 49, NKT64) - kt0; }
    else { A = g_bows16; B = g_disT16; lda = VP; ldb = VP;
           kt0 = blockIdx.z * 25; ktn = min(kt0 + 25, NKT64) - kt0; }

    auto issue = [&](int it) {
        const int k0 = (kt0 + it) * 64;
        const uint32_t st = sb + (it % 3) * STG64;
        #pragma unroll
        for (int i = 0; i < 4; i++) {
            int idx = i * 256 + tid;
            int r = idx >> 3, c = idx & 7;
            int ar = m0 + r;
            bool av = (!azf) || (ar < VV);
            cpa(st + r*P64 + c*16, A + (size_t)(av ? ar : 0)*lda + k0 + c*8, av ? 16 : 0);
            cpa(st + T64B + r*P64 + c*16, B + (size_t)(n0 + r)*ldb + k0 + c*8, 16);
        }
        CPCOMMIT();
    };

    float acc[2][8][4];
    #pragma unroll
    for (int mi = 0; mi < 2; mi++)
        #pragma unroll
        for (int ni = 0; ni < 8; ni++)
            #pragma unroll
            for (int q = 0; q < 4; q++) acc[mi][ni][q] = 0.f;

    const int nst = min(ktn, 3);
    for (int s = 0; s < nst; s++) issue(s);

    for (int it = 0; it < ktn; ++it) {
        const int rem = ktn - it - 1;
        if (rem >= 2) { CPWAIT(2); } else if (rem == 1) { CPWAIT(1); } else { CPWAIT(0); }
        __syncthreads();
        const uint32_t st = sb + (it % 3) * STG64;
        #pragma unroll
        for (int ks = 0; ks < 4; ks++) {
            uint32_t af[2][4], bfm[4][4];
            #pragma unroll
            for (int mi = 0; mi < 2; mi++) {
                int row = wm + mi*16 + (lane & 15);
                LDSM4(af[mi], st + row*P64 + (ks*2 + (lane >> 4))*16);
            }
            #pragma unroll
            for (int nj = 0; nj < 4; nj++) {
                int row = wn + nj*16 + (lane & 15);
                LDSM4(bfm[nj], st + T64B + row*P64 + (ks*2 + (lane >> 4))*16);
            }
            #pragma unroll
            for (int mi = 0; mi < 2; mi++)
                #pragma unroll
                for (int nj = 0; nj < 4; nj++) {
                    mma16816(acc[mi][nj*2],   af[mi], bfm[nj][0], bfm[nj][2]);
                    mma16816(acc[mi][nj*2+1], af[mi], bfm[nj][1], bfm[nj][3]);
                }
        }
        __syncthreads();
        if (it + 3 < ktn) issue(it + 3);
    }

    const int rq = lane >> 2, cq = (lane & 3) * 2;

    if constexpr (EPI == 0) {
        uint32_t* stg = (uint32_t*)smem;
        #pragma unroll
        for (int mi = 0; mi < 2; mi++)
            #pragma unroll
            for (int h = 0; h < 2; h++) {
                int lr = wm + mi*16 + rq + h*8;
                int row = m0 + lr;
                bool rv = row < VV;
                #pragma unroll
                for (int ni = 0; ni < 8; ni++) {
                    int lc = wn + ni*8 + cq;
                    float e0 = rv ? fminf(fmaxf(__expf(acc[mi][ni][2*h]),   1e-30f), 1e10f) : 0.f;
                    float e1 = rv ? fminf(fmaxf(__expf(acc[mi][ni][2*h+1]), 1e-30f), 1e10f) : 0.f;
                    uint32_t pkd = pk2(e0, e1);
                    stg[lr*65 + (lc >> 1)] = pkd;
                    if (rv) *reinterpret_cast<uint32_t*>(g_dis16 + (size_t)row*KP + n0 + lc) = pkd;
                }
            }
        __syncthreads();
        {
            const __nv_bfloat16* sg = (const __nv_bfloat16*)smem;
            int col = tid & 127, half = tid >> 7;
            float s = 0.f;
            #pragma unroll 8
            for (int r = 0; r < 64; r++)
                s += __bfloat162float(sg[(half*64 + r)*130 + col]);
            float* red = (float*)(smem + 33280);
            red[tid] = s;
            __syncthreads();
            if (tid < 128) g_Sp[blockIdx.x*KP + n0 + tid] = red[tid] + red[128 + tid];
        }
        {
            const __nv_bfloat16* sg = (const __nv_bfloat16*)smem;
            #pragma unroll
            for (int i = 0; i < 32; i++) {
                int idx = i*256 + tid;
                int c = idx >> 6, rp = idx & 63;
                __nv_bfloat16 a = sg[(2*rp)*130 + c];
                __nv_bfloat16 b = sg[(2*rp + 1)*130 + c];
                uint32_t val = ((uint32_t)__bfloat16_as_ushort(b) << 16) |
                                (uint32_t)__bfloat16_as_ushort(a);
                *reinterpret_cast<uint32_t*>(g_disT16 + (size_t)(n0 + c)*VP + m0 + 2*rp) = val;
            }
        }
    } else {
        constexpr int LDN = (EPI == 1) ? NH : KP;
        float* dst = ((EPI == 1) ? g_p1 : g_p2) + (size_t)blockIdx.z * BN * LDN;
        #pragma unroll
        for (int mi = 0; mi < 2; mi++)
            #pragma unroll
            for (int h = 0; h < 2; h++) {
                int row = m0 + wm + mi*16 + rq + h*8;
                #pragma unroll
                for (int ni = 0; ni < 8; ni++) {
                    int col = n0 + wn + ni*8 + cq;
                    float2 v = make_float2(acc[mi][ni][2*h], acc[mi][ni][2*h+1]);
                    *reinterpret_cast<float2*>(dst + (size_t)row*LDN + col) = v;
                }
            }
    }
}

// ---------------- merged den+recon (MUFU-starved epilogue), K=224, 2-stage ----------------
__global__ void __launch_bounds__(256) mm34() {
    extern __shared__ __align__(16) char dsm[];
    const uint32_t sb = s2u(dsm);
    const int tid = threadIdx.x, lane = tid & 31, wid = tid >> 5;
    const int wm = (wid & 3) * 32, wn = (wid >> 2) * 32;
    const int m0 = blockIdx.x * 128, n0 = blockIdx.y * 64;

    auto issue = [&](int it) {
        const int k0 = it * 32;
        const uint32_t st = sb + (it & 1) * STG34;
        #pragma unroll
        for (int i = 0; i < 2; i++) {
            int idx = i * 256 + tid;
            int r = idx >> 2, c = idx & 3;
            cpa(st + r*PITCH + c*16,         g_tn16  + (size_t)(m0 + r)*KP + k0 + c*8, 16);
            cpa(st + 10240 + r*PITCH + c*16, g_th216 + (size_t)(m0 + r)*KP + k0 + c*8, 16);
        }
        {
            int r = tid >> 2, c = tid & 3;
            int br = n0 + r;
            bool bv = br < VV;
            cpa(st + 20480 + r*PITCH + c*16, g_dis16 + (size_t)(bv ? br : 0)*KP + k0 + c*8, bv ? 16 : 0);
        }
        CPCOMMIT();
    };

    float a3[2][4][4], a4[2][4][4];
    #pragma unroll
    for (int mi = 0; mi < 2; mi++)
        #pragma unroll
        for (int ni = 0; ni < 4; ni++)
            #pragma unroll
            for (int q = 0; q < 4; q++) { a3[mi][ni][q] = 0.f; a4[mi][ni][q] = 0.f; }

    issue(0); issue(1);
    const int ktn = 7;
    for (int it = 0; it < ktn; ++it) {
        if (it == ktn - 1) { CPWAIT(0); } else { CPWAIT(1); }
        __syncthreads();
        const uint32_t st = sb + (it & 1) * STG34;
        #pragma unroll
        for (int ks = 0; ks < 2; ks++) {
            uint32_t af1[2][4], af2[2][4], bfm[2][4];
            #pragma unroll
            for (int mi = 0; mi < 2; mi++) {
                int row = wm + mi*16 + (lane & 15);
                uint32_t off = row*PITCH + (ks*2 + (lane >> 4))*16;
                LDSM4(af1[mi], st + off);
                LDSM4(af2[mi], st + 10240 + off);
            }
            #pragma unroll
            for (int nj = 0; nj < 2; nj++) {
                int row = wn + nj*16 + (lane & 15);
                LDSM4(bfm[nj], st + 20480 + row*PITCH + (ks*2 + (lane >> 4))*16);
            }
            #pragma unroll
            for (int mi = 0; mi < 2; mi++)
                #pragma unroll
                for (int nj = 0; nj < 2; nj++) {
                    mma16816(a3[mi][nj*2],   af1[mi], bfm[nj][0], bfm[nj][2]);
                    mma16816(a3[mi][nj*2+1], af1[mi], bfm[nj][1], bfm[nj][3]);
                    mma16816(a4[mi][nj*2],   af2[mi], bfm[nj][0], bfm[nj][2]);
                    mma16816(a4[mi][nj*2+1], af2[mi], bfm[nj][1], bfm[nj][3]);
                }
        }
        __syncthreads();
        if (it + 2 < ktn) issue(it + 2);
    }

    const int rq = lane >> 2, cq = (lane & 3) * 2;
    float nF = 0.f, sumR = 0.f, sumLG = 0.f;
    float prod = 1.f, acce = 0.f;
    #pragma unroll
    for (int mi = 0; mi < 2; mi++)
        #pragma unroll
        for (int h = 0; h < 2; h++) {
            int b = m0 + wm + mi*16 + rq + h*8;
            float inv = g_invn[b];
            float d[8], w[8], r[8];
            #pragma unroll
            for (int ni = 0; ni < 4; ni++) {
                int v = n0 + wn + ni*8 + cq;
                uint32_t wp = *reinterpret_cast<const uint32_t*>(g_bows16 + (size_t)b*VP + v);
                unp2(wp, w[ni*2], w[ni*2+1]);
                // w==0 lanes contribute 0 to the numerator; use d=1 to keep the
                // combined denominator product away from underflow (padded cols have den=0)
                d[ni*2]   = (w[ni*2]   != 0.f) ? a3[mi][ni][2*h]   + 1e-30f : 1.0f;
                d[ni*2+1] = (w[ni*2+1] != 0.f) ? a3[mi][ni][2*h+1] + 1e-30f : 1.0f;
                r[ni*2]   = a4[mi][ni][2*h];
                r[ni*2+1] = a4[mi][ni][2*h+1];
            }
            // forward: 8-way combined fraction -> one divide per row
            float n01 = w[0]*d[1] + w[1]*d[0], D01 = d[0]*d[1];
            float n23 = w[2]*d[3] + w[3]*d[2], D23 = d[2]*d[3];
            float n45 = w[4]*d[5] + w[5]*d[4], D45 = d[4]*d[5];
            float n67 = w[6]*d[7] + w[7]*d[6], D67 = d[6]*d[7];
            float nA = n01*D23 + n23*D01, DA = D01*D23;
            float nB = n45*D67 + n67*D45, DB = D45*D67;
            float Nn = nA*DB + nB*DA,     Dd = DA*DB;
            nF += inv * __fdividef(Nn, Dd);
            // poisson: sum r + lg(w) - w*log(r), logs batched via mantissa product
            #pragma unroll
            for (int j = 0; j < 8; j++) {
                float rr = r[j] + 1e-10f;
                sumR += r[j];
                int iw = (int)w[j];
                float lg = (iw == 2) ? 0.69314718055994531f
                         : (iw == 3) ? 1.79175946922805500f
                         : (iw == 4) ? 3.17805383034794562f : 0.f;
                sumLG += lg;
                int bits = __float_as_int(rr);
                int e = ((bits >> 23) & 0xFF) - 127;
                float m = __int_as_float((bits & 0x007FFFFF) | 0x3F800000);
                float m2 = m * m;
                float mw = 1.f;
                if (iw & 1) mw = m;
                if (iw & 2) mw *= m2;
                if (iw & 4) mw *= m2 * m2;
                prod *= mw;
                acce += (float)(iw * e);
                int pb = __float_as_int(prod);
                acce += (float)(((pb >> 23) & 0xFF) - 127);
                prod = __int_as_float((pb & 0x007FFFFF) | 0x3F800000);
            }
        }
    float nT = sumR + sumLG - 0.69314718055994531f * (acce + __log2f(prod));
    __syncthreads();
    float* red = (float*)dsm;
    red[tid] = nF; red[256 + tid] = nT;
    __syncthreads();
    for (int s = 128; s > 0; s >>= 1) {
        if (tid < s) { red[tid] += red[tid+s]; red[256+tid] += red[256+tid+s]; }
        __syncthreads();
    }
    if (tid == 0) {
        g_pF[blockIdx.y*4 + blockIdx.x] = red[0];
        g_pT[blockIdx.y*4 + blockIdx.x] = red[256];
    }
}

// ---------------- converters ----------------
__global__ void k_cvt_bows(const float* __restrict__ bows) {
    int b = blockIdx.x, tid = threadIdx.x;
    float s = 0.f;
    for (int i = tid; i < VP/8; i += 256) {
        int v = i * 8;
        uint4 o = make_uint4(0u,0u,0u,0u);
        if (v < VV) {
            const float4* p = reinterpret_cast<const float4*>(bows + (size_t)b*VV + v);
            float4 a = p[0], c = p[1];
            s += a.x+a.y+a.z+a.w + c.x+c.y+c.z+c.w;
            o.x = pk2(a.x,a.y); o.y = pk2(a.z,a.w); o.z = pk2(c.x,c.y); o.w = pk2(c.z,c.w);
        }
        reinterpret_cast<uint4*>(g_bows16)[(size_t)b*(VP/8) + i] = o;
    }
    __shared__ float red[256];
    red[tid] = s; __syncthreads();
    for (int st = 128; st > 0; st >>= 1) { if (tid < st) red[tid] += red[tid+st]; __syncthreads(); }
    if (tid == 0) { float n = red[0]; g_ntok[b] = n; g_invn[b] = (n > 0.f) ? 1.f/n : 0.f; }
}
__global__ void k_cvt_w1t(const float* __restrict__ W1) {
    __shared__ float t[64][65];
    int tx = threadIdx.x, ty = threadIdx.y;
    int v0 = blockIdx.x*64, h0 = blockIdx.y*64;
    #pragma unroll
    for (int i = 0; i < 8; i++) {
        int r = ty + i*8;
        int gv = v0 + r;
        t[r][tx]    = (gv < VV && h0+tx    < HIDD) ? W1[(size_t)gv*HIDD + h0+tx]    : 0.f;
        t[r][tx+32] = (gv < VV && h0+tx+32 < HIDD) ? W1[(size_t)gv*HIDD + h0+tx+32] : 0.f;
    }
    __syncthreads();
    #pragma unroll
    for (int i = 0; i < 8; i++) {
        int r = ty + i*8;
        uint32_t val = pk2(t[2*tx][r], t[2*tx+1][r]);
        *reinterpret_cast<uint32_t*>(g_w1t + (size_t)(h0+r)*VP + v0 + 2*tx) = val;
    }
}
__global__ void k_cvt_rho(const float* __restrict__ rho) {
    int i = blockIdx.x*256 + threadIdx.x;
    if (i >= VV*(HP/4)) return;
    int r = i / (HP/4);
    int c = (i % (HP/4)) * 4;
    uint2 o = make_uint2(0u, 0u);
    if (c < HH) {
        float4 v = *reinterpret_cast<const float4*>(rho + (size_t)r*HH + c);
        o.x = pk2(v.x, v.y); o.y = pk2(v.z, v.w);
    }
    *reinterpret_cast<uint2*>(g_rho16 + (size_t)r*HP + c) = o;
}
__global__ void k_cvt_al(const float* __restrict__ al) {
    int i = blockIdx.x*256 + threadIdx.x;
    if (i >= KP*(HP/4)) return;
    int r = i / (HP/4);
    int c = (i % (HP/4)) * 4;
    uint2 o = make_uint2(0u, 0u);
    if (r < KK && c < HH) {
        float4 v = *reinterpret_cast<const float4*>(al + (size_t)r*HH + c);
        o.x = pk2(v.x, v.y); o.y = pk2(v.z, v.w);
    }
    *reinterpret_cast<uint2*>(g_al16 + (size_t)r*HP + c) = o;
}

// ---------------- small kernels ----------------
__global__ void k_sr() {
    int k = blockIdx.x, t = threadIdx.x;
    float s = 0.f;
    for (int i = t; i < MT; i += 128) s += g_Sp[i*KP + k];
    __shared__ float red[128];
    red[t] = s; __syncthreads();
    for (int st = 64; st > 0; st >>= 1) { if (t < st) red[t] += red[t+st]; __syncthreads(); }
    if (t == 0) g_S[k] = red[0];
}
__global__ void k1_reduce(const float* __restrict__ b1) {
    int idx = blockIdx.x*256 + threadIdx.x;
    if (idx >= BN*HIDD) return;
    int b = idx / HIDD, h = idx % HIDD;
    float s = 0.f;
    #pragma unroll
    for (int z = 0; z < Z1; z++) s += g_p1[(size_t)z*BN*NH + (size_t)b*NH + h];
    g_hid[idx] = fmaxf(s + b1[h], 0.f);
}
__global__ void k_mlp2(const float* __restrict__ W2, const float* __restrict__ b2) {
    __shared__ __align__(16) float As[16][68];
    __shared__ __align__(16) float Bs[16][68];
    const int tid = threadIdx.x, tx = tid & 15, ty = tid >> 4;
    const int m0 = blockIdx.y*64, n0 = blockIdx.x*64;
    const int ar = tid >> 2, ac = (tid & 3) << 2;
    const int br = tid >> 4, bc = (tid & 15) << 2;
    float acc[4][4];
    #pragma unroll
    for (int i = 0; i < 4; i++)
        #pragma unroll
        for (int j = 0; j < 4; j++) acc[i][j] = 0.f;
    for (int kt = 0; kt < 50; ++kt) {
        int k0 = kt*16;
        float4 va = *reinterpret_cast<const float4*>(g_hid + (size_t)(m0+ar)*HIDD + k0 + ac);
        As[ac+0][ar] = va.x; As[ac+1][ar] = va.y; As[ac+2][ar] = va.z; As[ac+3][ar] = va.w;
        float4 vb = make_float4(0.f,0.f,0.f,0.f);
        int gn = n0 + bc;
        const float* bp = W2 + (size_t)(k0+br)*KK + gn;
        if (gn + 3 < KK) vb = *reinterpret_cast<const float4*>(bp);
        else { if (gn<KK) vb.x=bp[0]; if (gn+1<KK) vb.y=bp[1]; if (gn+2<KK) vb.z=bp[2]; }
        *reinterpret_cast<float4*>(&Bs[br][bc]) = vb;
        __syncthreads();
        #pragma unroll
        for (int k = 0; k < 16; k++) {
            float4 a = *reinterpret_cast<const float4*>(&As[k][ty << 2]);
            float4 b = *reinterpret_cast<const float4*>(&Bs[k][tx << 2]);
            float av[4] = {a.x,a.y,a.z,a.w}, bv[4] = {b.x,b.y,b.z,b.w};
            #pragma unroll
            for (int i = 0; i < 4; i++)
                #pragma unroll
                for (int j = 0; j < 4; j++) acc[i][j] = fmaf(av[i], bv[j], acc[i][j]);
        }
        __syncthreads();
    }
    #pragma unroll
    for (int i = 0; i < 4; i++) {
        int m = m0 + (ty << 2) + i;
        #pragma unroll
        for (int j = 0; j < 4; j++) {
            int n = n0 + (tx << 2) + j;
            if (n < KK) {
                float x = acc[i][j] + b2[n];
                g_theta[(size_t)m*KK + n] = fmaxf(x, 0.f) + log1pf(expf(-fabsf(x)));
            }
        }
    }
}
__global__ void k_soft2() {
    int b = blockIdx.x, t = threadIdx.x;
    __shared__ float red[256];
    float th = (t < KK) ? g_theta[(size_t)b*KK + t] : -1e30f;
    red[t] = th; __syncthreads();
    for (int s = 128; s > 0; s >>= 1) { if (t < s) red[t] = fmaxf(red[t], red[t+s]); __syncthreads(); }
    float mx = red[0]; __syncthreads();
    float e = (t < KK) ? expf(th - mx) : 0.f;
    red[t] = e; __syncthreads();
    for (int s = 128; s > 0; s >>= 1) { if (t < s) red[t] += red[t+s]; __syncthreads(); }
    float tn = e / red[0];
    if (t < KK) g_tn[(size_t)b*KK + t] = tn;
    g_tn16[(size_t)b*KP + t]  = (t < KK) ? __float2bfloat16_rn(tn) : __nv_bfloat16(0.f);
    g_th216[(size_t)b*KP + t] = (t < KK) ? __float2bfloat16_rn(th / g_S[t]) : __nv_bfloat16(0.f);
}
__global__ void k4bwd() {
    int b = blockIdx.x, t = threadIdx.x;
    float local = 0.f;
    if (t < KK) {
        float cs = 0.f;
        #pragma unroll
        for (int z = 0; z < Z2; z++) cs += g_p2[(size_t)z*BN*KP + (size_t)b*KP + t];
        local = g_ntok[b] * g_tn[(size_t)b*KK + t] / (cs + 1e-30f);
    }
    __shared__ float red[256];
    red[t] = local; __syncthreads();
    for (int s = 128; s > 0; s >>= 1) { if (t < s) red[t] += red[t+s]; __syncthreads(); }
    if (t == 0) g_pB[b] = red[0];
}
__global__ void k_final(float* __restrict__ out) {
    int t = threadIdx.x;
    __shared__ double red[256];
    double s = 0.0;
    for (int i = t; i < NP2; i += 256) s += (double)g_pF[i];
    red[t] = s; __syncthreads();
    for (int st = 128; st > 0; st >>= 1) { if (t < st) red[t] += red[t+st]; __syncthreads(); }
    double fwd = red[0]; __syncthreads();
    s = 0.0;
    for (int i = t; i < NP2; i += 256) s += (double)g_pT[i];
    red[t] = s; __syncthreads();
    for (int st = 128; st > 0; st >>= 1) { if (t < st) red[t] += red[t+st]; __syncthreads(); }
    double tm = red[0]; __syncthreads();
    s = 0.0;
    for (int i = t; i < BN; i += 256) s += (double)g_pB[i];
    red[t] = s; __syncthreads();
    for (int st = 128; st > 0; st >>= 1) { if (t < st) red[t] += red[t+st]; __syncthreads(); }
    double bwd = red[0];
    if (t == 0) {
        out[0] = (float)(tm / (double)BN);
        out[1] = (float)(0.5 * fwd);
        out[2] = (float)(0.5 * bwd);
    }
}

// ---------------- launch (three-stream fork/join) ----------------
extern "C" void kernel_launch(void* const* d_in, const int* in_sizes, int n_in,
                              void* d_out, int out_size) {
    const float* bows  = (const float*)d_in[0];
    const float* rho   = (const float*)d_in[1];
    const float* alpha = (const float*)d_in[2];
    const float* W1    = (const float*)d_in[3];
    const float* b1    = (const float*)d_in[4];
    const float* W2    = (const float*)d_in[5];
    const float* b2    = (const float*)d_in[6];
    float* out = (float*)d_out;

    static cudaStream_t s1 = nullptr, s2 = nullptr;
    static cudaEvent_t evF, evB, evS, evJ, evW;
    if (!s1) {
        cudaStreamCreateWithFlags(&s1, cudaStreamNonBlocking);
        cudaStreamCreateWithFlags(&s2, cudaStreamNonBlocking);
        cudaEventCreateWithFlags(&evF, cudaEventDisableTiming);
        cudaEventCreateWithFlags(&evB, cudaEventDisableTiming);
        cudaEventCreateWithFlags(&evS, cudaEventDisableTiming);
        cudaEventCreateWithFlags(&evJ, cudaEventDisableTiming);
        cudaEventCreateWithFlags(&evW, cudaEventDisableTiming);
        cudaFuncSetAttribute(mm<0>, cudaFuncAttributeMaxDynamicSharedMemorySize, MMS);
        cudaFuncSetAttribute(mm<1>, cudaFuncAttributeMaxDynamicSharedMemorySize, MMS);
        cudaFuncSetAttribute(mm<2>, cudaFuncAttributeMaxDynamicSharedMemorySize, MMS);
        cudaFuncSetAttribute(mm34, cudaFuncAttributeMaxDynamicSharedMemorySize, 2*STG34);
    }

    // fork
    cudaEventRecord(evF, 0);
    cudaStreamWaitEvent(s1, evF, 0);
    cudaStreamWaitEvent(s2, evF, 0);

    // chain A (s1)
    k_cvt_rho<<<(VV*(HP/4) + 255)/256, 256, 0, s1>>>(rho);
    k_cvt_al<<<(KP*(HP/4) + 255)/256, 256, 0, s1>>>(alpha);
    mm<0><<<dim3(MT, 2), 256, MMS, s1>>>();
    k_sr<<<KP, 128, 0, s1>>>();
    cudaEventRecord(evS, s1);

    // chain C (s2)
    k_cvt_w1t<<<dim3(VP/64, NH/64), dim3(32, 8), 0, s2>>>(W1);
    cudaEventRecord(evW, s2);

    // chain B (default)
    k_cvt_bows<<<BN, 256>>>(bows);
    cudaEventRecord(evB, 0);

    // chain A continues
    cudaStreamWaitEvent(s1, evB, 0);
    mm<2><<<dim3(4, 2, Z2), 256, MMS, s1>>>();
    cudaEventRecord(evJ, s1);

    // chain B
    cudaStreamWaitEvent(0, evW, 0);
    mm<1><<<dim3(4, 7, Z1), 256, MMS>>>();
    k1_reduce<<<(BN*HIDD + 255)/256, 256>>>(b1);
    k_mlp2<<<dim3(4, 8), 256>>>(W2, b2);

    // joins
    cudaStreamWaitEvent(0, evS, 0);
    k_soft2<<<BN, 256>>>();
    cudaStreamWaitEvent(0, evJ, 0);
    k4bwd<<<BN, 256>>>();

    mm34<<<dim3(4, NT64), 256, 2*STG34>>>();

    k_final<<<1, 256>>>(out);
}

// round 17
// speedup vs baseline: 1.0624x; 1.0624x over previous
#include <cuda_runtime.h>
#include <cuda_bf16.h>
#include <math.h>
#include <stdint.h>

#define BN 512
#define VV 50000
#define KK 200
#define HH 300
#define HIDD 800
#define VP 50048
#define KP 256
#define HP 320
#define NH 896
#define Z1 16
#define Z2 32
#define NKT64 (VP/64)          // 782 k64-tiles over vocab
#define MT ((VV+127)/128)      // 391
#define NT64 (VP/64)           // 782 n-tiles for mm34
#define NP2 (NT64*4)

// ---------------- scratch ----------------
__device__ __align__(16) __nv_bfloat16 g_bows16[(size_t)BN*VP];
__device__ __align__(16) __nv_bfloat16 g_w1t[(size_t)NH*VP];
__device__ __align__(16) __nv_bfloat16 g_rho16[(size_t)VV*HP];
__device__ __align__(16) __nv_bfloat16 g_al16[(size_t)KP*HP];
__device__ __align__(16) __nv_bfloat16 g_dis16[(size_t)VV*KP];
__device__ __align__(16) __nv_bfloat16 g_disT16[(size_t)KP*VP];
__device__ __align__(16) __nv_bfloat16 g_tn16[(size_t)BN*KP];
__device__ __align__(16) __nv_bfloat16 g_th216[(size_t)BN*KP];
__device__ float g_p1[(size_t)Z1*BN*NH];
__device__ float g_p2[(size_t)Z2*BN*KP];
__device__ float g_hid[BN*HIDD];
__device__ float g_theta[BN*KK];
__device__ float g_tn[BN*KK];
__device__ float g_ntok[BN];
__device__ float g_invn[BN];
__device__ float g_S[KP];
__device__ float g_Sp[MT*KP];
__device__ float g_pF[NP2];
__device__ float g_pT[NP2];
__device__ float g_pB[BN];

__constant__ float c_lg[5] = {0.0f, 0.0f, 0.69314718055994531f,
                              1.79175946922805500f, 3.17805383034794562f};

// ---------------- helpers ----------------
__device__ __forceinline__ uint32_t s2u(const void* p) {
    uint32_t a;
    asm("{ .reg .u64 t; cvta.to.shared.u64 t, %1; cvt.u32.u64 %0, t; }" : "=r"(a) : "l"(p));
    return a;
}
__device__ __forceinline__ void cpa(uint32_t sa, const void* ga, int sz) {
    asm volatile("cp.async.cg.shared.global [%0], [%1], 16, %2;"
                 :: "r"(sa), "l"(ga), "r"(sz) : "memory");
}
#define CPCOMMIT() asm volatile("cp.async.commit_group;" ::: "memory")
#define CPWAIT(n)  asm volatile("cp.async.wait_group %0;" :: "n"(n) : "memory")
#define LDSM4(r, a) \
    asm volatile("ldmatrix.sync.aligned.m8n8.x4.shared.b16 {%0,%1,%2,%3}, [%4];" \
        : "=r"((r)[0]), "=r"((r)[1]), "=r"((r)[2]), "=r"((r)[3]) : "r"(a))

__device__ __forceinline__ void mma16816(float* c, const uint32_t* a, uint32_t b0, uint32_t b1) {
    asm volatile("mma.sync.aligned.m16n8k16.row.col.f32.bf16.bf16.f32 "
        "{%0,%1,%2,%3}, {%4,%5,%6,%7}, {%8,%9}, {%0,%1,%2,%3};"
        : "+f"(c[0]), "+f"(c[1]), "+f"(c[2]), "+f"(c[3])
        : "r"(a[0]), "r"(a[1]), "r"(a[2]), "r"(a[3]), "r"(b0), "r"(b1));
}
__device__ __forceinline__ void unp2(uint32_t u, float& a, float& b) {
    __nv_bfloat162 t = *reinterpret_cast<__nv_bfloat162*>(&u);
    a = __bfloat162float(t.x); b = __bfloat162float(t.y);
}
__device__ __forceinline__ uint32_t pk2(float a, float b) {
    return ((uint32_t)__bfloat16_as_ushort(__float2bfloat16_rn(b)) << 16) |
            (uint32_t)__bfloat16_as_ushort(__float2bfloat16_rn(a));
}

// mm template: K-tile 64, pitch 144
#define P64 144
#define T64B (128*P64)
#define STG64 (2*T64B)
#define MMS (3*STG64)

// mm34: K-tile 32, pitch 80 (2-stage)
#define PITCH 80
#define STG34 25600

// ---------------- bf16 HMMA GEMM template (K64, 3-stage) ----------------
template<int EPI>
__global__ void __launch_bounds__(256) mm() {
    extern __shared__ __align__(16) char smem[];
    const uint32_t sb = s2u(smem);
    const int tid = threadIdx.x, lane = tid & 31, wid = tid >> 5;
    const int wm = (wid & 3) * 32, wn = (wid >> 2) * 64;
    const int m0 = blockIdx.x * 128, n0 = blockIdx.y * 128;

    const __nv_bfloat16 *A, *B;
    int lda, ldb, kt0, ktn;
    bool azf = false;
    if (EPI == 0) { A = g_rho16; B = g_al16; lda = HP; ldb = HP; kt0 = 0; ktn = HP/64; azf = true; }
    else if (EPI == 1) { A = g_bows16; B = g_w1t; lda = VP; ldb = VP;
                         kt0 = blockIdx.z * 49; ktn = min(kt0 + 49, NKT64) - kt0; }
    else { A = g_bows16; B = g_disT16; lda = VP; ldb = VP;
           kt0 = blockIdx.z * 25; ktn = min(kt0 + 25, NKT64) - kt0; }

    auto issue = [&](int it) {
        const int k0 = (kt0 + it) * 64;
        const uint32_t st = sb + (it % 3) * STG64;
        #pragma unroll
        for (int i = 0; i < 4; i++) {
            int idx = i * 256 + tid;
            int r = idx >> 3, c = idx & 7;
            int ar = m0 + r;
            bool av = (!azf) || (ar < VV);
            cpa(st + r*P64 + c*16, A + (size_t)(av ? ar : 0)*lda + k0 + c*8, av ? 16 : 0);
            cpa(st + T64B + r*P64 + c*16, B + (size_t)(n0 + r)*ldb + k0 + c*8, 16);
        }
        CPCOMMIT();
    };

    float acc[2][8][4];
    #pragma unroll
    for (int mi = 0; mi < 2; mi++)
        #pragma unroll
        for (int ni = 0; ni < 8; ni++)
            #pragma unroll
            for (int q = 0; q < 4; q++) acc[mi][ni][q] = 0.f;

    const int nst = min(ktn, 3);
    for (int s = 0; s < nst; s++) issue(s);

    for (int it = 0; it < ktn; ++it) {
        const int rem = ktn - it - 1;
        if (rem >= 2) { CPWAIT(2); } else if (rem == 1) { CPWAIT(1); } else { CPWAIT(0); }
        __syncthreads();
        const uint32_t st = sb + (it % 3) * STG64;
        #pragma unroll
        for (int ks = 0; ks < 4; ks++) {
            uint32_t af[2][4], bfm[4][4];
            #pragma unroll
            for (int mi = 0; mi < 2; mi++) {
                int row = wm + mi*16 + (lane & 15);
                LDSM4(af[mi], st + row*P64 + (ks*2 + (lane >> 4))*16);
            }
            #pragma unroll
            for (int nj = 0; nj < 4; nj++) {
                int row = wn + nj*16 + (lane & 15);
                LDSM4(bfm[nj], st + T64B + row*P64 + (ks*2 + (lane >> 4))*16);
            }
            #pragma unroll
            for (int mi = 0; mi < 2; mi++)
                #pragma unroll
                for (int nj = 0; nj < 4; nj++) {
                    mma16816(acc[mi][nj*2],   af[mi], bfm[nj][0], bfm[nj][2]);
                    mma16816(acc[mi][nj*2+1], af[mi], bfm[nj][1], bfm[nj][3]);
                }
        }
        __syncthreads();
        if (it + 3 < ktn) issue(it + 3);
    }

    const int rq = lane >> 2, cq = (lane & 3) * 2;

    if constexpr (EPI == 0) {
        uint32_t* stg = (uint32_t*)smem;
        #pragma unroll
        for (int mi = 0; mi < 2; mi++)
            #pragma unroll
            for (int h = 0; h < 2; h++) {
                int lr = wm + mi*16 + rq + h*8;
                int row = m0 + lr;
                bool rv = row < VV;
                #pragma unroll
                for (int ni = 0; ni < 8; ni++) {
                    int lc = wn + ni*8 + cq;
                    float e0 = rv ? fminf(fmaxf(__expf(acc[mi][ni][2*h]),   1e-30f), 1e10f) : 0.f;
                    float e1 = rv ? fminf(fmaxf(__expf(acc[mi][ni][2*h+1]), 1e-30f), 1e10f) : 0.f;
                    uint32_t pkd = pk2(e0, e1);
                    stg[lr*65 + (lc >> 1)] = pkd;
                    if (rv) *reinterpret_cast<uint32_t*>(g_dis16 + (size_t)row*KP + n0 + lc) = pkd;
                }
            }
        __syncthreads();
        {
            const __nv_bfloat16* sg = (const __nv_bfloat16*)smem;
            int col = tid & 127, half = tid >> 7;
            float s = 0.f;
            #pragma unroll 8
            for (int r = 0; r < 64; r++)
                s += __bfloat162float(sg[(half*64 + r)*130 + col]);
            float* red = (float*)(smem + 33280);
            red[tid] = s;
            __syncthreads();
            if (tid < 128) g_Sp[blockIdx.x*KP + n0 + tid] = red[tid] + red[128 + tid];
        }
        {
            const __nv_bfloat16* sg = (const __nv_bfloat16*)smem;
            #pragma unroll
            for (int i = 0; i < 32; i++) {
                int idx = i*256 + tid;
                int c = idx >> 6, rp = idx & 63;
                __nv_bfloat16 a = sg[(2*rp)*130 + c];
                __nv_bfloat16 b = sg[(2*rp + 1)*130 + c];
                uint32_t val = ((uint32_t)__bfloat16_as_ushort(b) << 16) |
                                (uint32_t)__bfloat16_as_ushort(a);
                *reinterpret_cast<uint32_t*>(g_disT16 + (size_t)(n0 + c)*VP + m0 + 2*rp) = val;
            }
        }
    } else {
        constexpr int LDN = (EPI == 1) ? NH : KP;
        float* dst = ((EPI == 1) ? g_p1 : g_p2) + (size_t)blockIdx.z * BN * LDN;
        #pragma unroll
        for (int mi = 0; mi < 2; mi++)
            #pragma unroll
            for (int h = 0; h < 2; h++) {
                int row = m0 + wm + mi*16 + rq + h*8;
                #pragma unroll
                for (int ni = 0; ni < 8; ni++) {
                    int col = n0 + wn + ni*8 + cq;
                    float2 v = make_float2(acc[mi][ni][2*h], acc[mi][ni][2*h+1]);
                    *reinterpret_cast<float2*>(dst + (size_t)row*LDN + col) = v;
                }
            }
    }
}

// ---------------- merged den+recon (dual accumulator, R14 epilogue), K=224, 2-stage ----------------
__global__ void __launch_bounds__(256) mm34() {
    extern __shared__ __align__(16) char dsm[];
    const uint32_t sb = s2u(dsm);
    const int tid = threadIdx.x, lane = tid & 31, wid = tid >> 5;
    const int wm = (wid & 3) * 32, wn = (wid >> 2) * 32;
    const int m0 = blockIdx.x * 128, n0 = blockIdx.y * 64;

    auto issue = [&](int it) {
        const int k0 = it * 32;
        const uint32_t st = sb + (it & 1) * STG34;
        #pragma unroll
        for (int i = 0; i < 2; i++) {
            int idx = i * 256 + tid;
            int r = idx >> 2, c = idx & 3;
            cpa(st + r*PITCH + c*16,         g_tn16  + (size_t)(m0 + r)*KP + k0 + c*8, 16);
            cpa(st + 10240 + r*PITCH + c*16, g_th216 + (size_t)(m0 + r)*KP + k0 + c*8, 16);
        }
        {
            int r = tid >> 2, c = tid & 3;
            int br = n0 + r;
            bool bv = br < VV;
            cpa(st + 20480 + r*PITCH + c*16, g_dis16 + (size_t)(bv ? br : 0)*KP + k0 + c*8, bv ? 16 : 0);
        }
        CPCOMMIT();
    };

    float a3[2][4][4], a4[2][4][4];
    #pragma unroll
    for (int mi = 0; mi < 2; mi++)
        #pragma unroll
        for (int ni = 0; ni < 4; ni++)
            #pragma unroll
            for (int q = 0; q < 4; q++) { a3[mi][ni][q] = 0.f; a4[mi][ni][q] = 0.f; }

    issue(0); issue(1);
    const int ktn = 7;
    for (int it = 0; it < ktn; ++it) {
        if (it == ktn - 1) { CPWAIT(0); } else { CPWAIT(1); }
        __syncthreads();
        const uint32_t st = sb + (it & 1) * STG34;
        #pragma unroll
        for (int ks = 0; ks < 2; ks++) {
            uint32_t af1[2][4], af2[2][4], bfm[2][4];
            #pragma unroll
            for (int mi = 0; mi < 2; mi++) {
                int row = wm + mi*16 + (lane & 15);
                uint32_t off = row*PITCH + (ks*2 + (lane >> 4))*16;
                LDSM4(af1[mi], st + off);
                LDSM4(af2[mi], st + 10240 + off);
            }
            #pragma unroll
            for (int nj = 0; nj < 2; nj++) {
                int row = wn + nj*16 + (lane & 15);
                LDSM4(bfm[nj], st + 20480 + row*PITCH + (ks*2 + (lane >> 4))*16);
            }
            #pragma unroll
            for (int mi = 0; mi < 2; mi++)
                #pragma unroll
                for (int nj = 0; nj < 2; nj++) {
                    mma16816(a3[mi][nj*2],   af1[mi], bfm[nj][0], bfm[nj][2]);
                    mma16816(a3[mi][nj*2+1], af1[mi], bfm[nj][1], bfm[nj][3]);
                    mma16816(a4[mi][nj*2],   af2[mi], bfm[nj][0], bfm[nj][2]);
                    mma16816(a4[mi][nj*2+1], af2[mi], bfm[nj][1], bfm[nj][3]);
                }
        }
        __syncthreads();
        if (it + 2 < ktn) issue(it + 2);
    }

    const int rq = lane >> 2, cq = (lane & 3) * 2;
    float nF = 0.f, nT = 0.f;
    #pragma unroll
    for (int mi = 0; mi < 2; mi++)
        #pragma unroll
        for (int h = 0; h < 2; h++) {
            int b = m0 + wm + mi*16 + rq + h*8;
            float inv = g_invn[b];
            #pragma unroll
            for (int ni = 0; ni < 4; ni++) {
                int v = n0 + wn + ni*8 + cq;
                uint32_t wp = *reinterpret_cast<const uint32_t*>(g_bows16 + (size_t)b*VP + v);
                float w0, w1; unp2(wp, w0, w1);
                float d0 = a3[mi][ni][2*h], d1 = a3[mi][ni][2*h+1];
                float r0 = a4[mi][ni][2*h], r1 = a4[mi][ni][2*h+1];
                if (w0 != 0.f) {
                    nF += __fdividef(w0 * inv, d0 + 1e-30f);
                    nT += r0 + c_lg[(int)w0] - w0 * __logf(r0 + 1e-10f);
                } else nT += r0;
                if (w1 != 0.f) {
                    nF += __fdividef(w1 * inv, d1 + 1e-30f);
                    nT += r1 + c_lg[(int)w1] - w1 * __logf(r1 + 1e-10f);
                } else nT += r1;
            }
        }
    __syncthreads();
    float* red = (float*)dsm;
    red[tid] = nF; red[256 + tid] = nT;
    __syncthreads();
    for (int s = 128; s > 0; s >>= 1) {
        if (tid < s) { red[tid] += red[tid+s]; red[256+tid] += red[256+tid+s]; }
        __syncthreads();
    }
    if (tid == 0) {
        g_pF[blockIdx.y*4 + blockIdx.x] = red[0];
        g_pT[blockIdx.y*4 + blockIdx.x] = red[256];
    }
}

// ---------------- converters ----------------
__global__ void k_cvt_bows(const float* __restrict__ bows) {
    int b = blockIdx.x, tid = threadIdx.x;
    float s = 0.f;
    for (int i = tid; i < VP/8; i += 256) {
        int v = i * 8;
        uint4 o = make_uint4(0u,0u,0u,0u);
        if (v < VV) {
            const float4* p = reinterpret_cast<const float4*>(bows + (size_t)b*VV + v);
            float4 a = p[0], c = p[1];
            s += a.x+a.y+a.z+a.w + c.x+c.y+c.z+c.w;
            o.x = pk2(a.x,a.y); o.y = pk2(a.z,a.w); o.z = pk2(c.x,c.y); o.w = pk2(c.z,c.w);
        }
        reinterpret_cast<uint4*>(g_bows16)[(size_t)b*(VP/8) + i] = o;
    }
    __shared__ float red[256];
    red[tid] = s; __syncthreads();
    for (int st = 128; st > 0; st >>= 1) { if (tid < st) red[tid] += red[tid+st]; __syncthreads(); }
    if (tid == 0) { float n = red[0]; g_ntok[b] = n; g_invn[b] = (n > 0.f) ? 1.f/n : 0.f; }
}
__global__ void k_cvt_w1t(const float* __restrict__ W1) {
    __shared__ float t[64][65];
    int tx = threadIdx.x, ty = threadIdx.y;
    int v0 = blockIdx.x*64, h0 = blockIdx.y*64;
    #pragma unroll
    for (int i = 0; i < 8; i++) {
        int r = ty + i*8;
        int gv = v0 + r;
        t[r][tx]    = (gv < VV && h0+tx    < HIDD) ? W1[(size_t)gv*HIDD + h0+tx]    : 0.f;
        t[r][tx+32] = (gv < VV && h0+tx+32 < HIDD) ? W1[(size_t)gv*HIDD + h0+tx+32] : 0.f;
    }
    __syncthreads();
    #pragma unroll
    for (int i = 0; i < 8; i++) {
        int r = ty + i*8;
        uint32_t val = pk2(t[2*tx][r], t[2*tx+1][r]);
        *reinterpret_cast<uint32_t*>(g_w1t + (size_t)(h0+r)*VP + v0 + 2*tx) = val;
    }
}
__global__ void k_cvt_rho(const float* __restrict__ rho) {
    int i = blockIdx.x*256 + threadIdx.x;
    if (i >= VV*(HP/4)) return;
    int r = i / (HP/4);
    int c = (i % (HP/4)) * 4;
    uint2 o = make_uint2(0u, 0u);
    if (c < HH) {
        float4 v = *reinterpret_cast<const float4*>(rho + (size_t)r*HH + c);
        o.x = pk2(v.x, v.y); o.y = pk2(v.z, v.w);
    }
    *reinterpret_cast<uint2*>(g_rho16 + (size_t)r*HP + c) = o;
}
__global__ void k_cvt_al(const float* __restrict__ al) {
    int i = blockIdx.x*256 + threadIdx.x;
    if (i >= KP*(HP/4)) return;
    int r = i / (HP/4);
    int c = (i % (HP/4)) * 4;
    uint2 o = make_uint2(0u, 0u);
    if (r < KK && c < HH) {
        float4 v = *reinterpret_cast<const float4*>(al + (size_t)r*HH + c);
        o.x = pk2(v.x, v.y); o.y = pk2(v.z, v.w);
    }
    *reinterpret_cast<uint2*>(g_al16 + (size_t)r*HP + c) = o;
}

// ---------------- small kernels ----------------
__global__ void k_sr() {
    int k = blockIdx.x, t = threadIdx.x;
    float s = 0.f;
    for (int i = t; i < MT; i += 128) s += g_Sp[i*KP + k];
    __shared__ float red[128];
    red[t] = s; __syncthreads();
    for (int st = 64; st > 0; st >>= 1) { if (t < st) red[t] += red[t+st]; __syncthreads(); }
    if (t == 0) g_S[k] = red[0];
}
__global__ void k1_reduce(const float* __restrict__ b1) {
    int idx = blockIdx.x*256 + threadIdx.x;
    if (idx >= BN*HIDD) return;
    int b = idx / HIDD, h = idx % HIDD;
    float s = 0.f;
    #pragma unroll
    for (int z = 0; z < Z1; z++) s += g_p1[(size_t)z*BN*NH + (size_t)b*NH + h];
    g_hid[idx] = fmaxf(s + b1[h], 0.f);
}
__global__ void k_mlp2(const float* __restrict__ W2, const float* __restrict__ b2) {
    __shared__ __align__(16) float As[16][68];
    __shared__ __align__(16) float Bs[16][68];
    const int tid = threadIdx.x, tx = tid & 15, ty = tid >> 4;
    const int m0 = blockIdx.y*64, n0 = blockIdx.x*64;
    const int ar = tid >> 2, ac = (tid & 3) << 2;
    const int br = tid >> 4, bc = (tid & 15) << 2;
    float acc[4][4];
    #pragma unroll
    for (int i = 0; i < 4; i++)
        #pragma unroll
        for (int j = 0; j < 4; j++) acc[i][j] = 0.f;
    for (int kt = 0; kt < 50; ++kt) {
        int k0 = kt*16;
        float4 va = *reinterpret_cast<const float4*>(g_hid + (size_t)(m0+ar)*HIDD + k0 + ac);
        As[ac+0][ar] = va.x; As[ac+1][ar] = va.y; As[ac+2][ar] = va.z; As[ac+3][ar] = va.w;
        float4 vb = make_float4(0.f,0.f,0.f,0.f);
        int gn = n0 + bc;
        const float* bp = W2 + (size_t)(k0+br)*KK + gn;
        if (gn + 3 < KK) vb = *reinterpret_cast<const float4*>(bp);
        else { if (gn<KK) vb.x=bp[0]; if (gn+1<KK) vb.y=bp[1]; if (gn+2<KK) vb.z=bp[2]; }
        *reinterpret_cast<float4*>(&Bs[br][bc]) = vb;
        __syncthreads();
        #pragma unroll
        for (int k = 0; k < 16; k++) {
            float4 a = *reinterpret_cast<const float4*>(&As[k][ty << 2]);
            float4 b = *reinterpret_cast<const float4*>(&Bs[k][tx << 2]);
            float av[4] = {a.x,a.y,a.z,a.w}, bv[4] = {b.x,b.y,b.z,b.w};
            #pragma unroll
            for (int i = 0; i < 4; i++)
                #pragma unroll
                for (int j = 0; j < 4; j++) acc[i][j] = fmaf(av[i], bv[j], acc[i][j]);
        }
        __syncthreads();
    }
    #pragma unroll
    for (int i = 0; i < 4; i++) {
        int m = m0 + (ty << 2) + i;
        #pragma unroll
        for (int j = 0; j < 4; j++) {
            int n = n0 + (tx << 2) + j;
            if (n < KK) {
                float x = acc[i][j] + b2[n];
                g_theta[(size_t)m*KK + n] = fmaxf(x, 0.f) + log1pf(expf(-fabsf(x)));
            }
        }
    }
}
__global__ void k_soft2() {
    int b = blockIdx.x, t = threadIdx.x;
    __shared__ float red[256];
    float th = (t < KK) ? g_theta[(size_t)b*KK + t] : -1e30f;
    red[t] = th; __syncthreads();
    for (int s = 128; s > 0; s >>= 1) { if (t < s) red[t] = fmaxf(red[t], red[t+s]); __syncthreads(); }
    float mx = red[0]; __syncthreads();
    float e = (t < KK) ? expf(th - mx) : 0.f;
    red[t] = e; __syncthreads();
    for (int s = 128; s > 0; s >>= 1) { if (t < s) red[t] += red[t+s]; __syncthreads(); }
    float tn = e / red[0];
    if (t < KK) g_tn[(size_t)b*KK + t] = tn;
    g_tn16[(size_t)b*KP + t]  = (t < KK) ? __float2bfloat16_rn(tn) : __nv_bfloat16(0.f);
    g_th216[(size_t)b*KP + t] = (t < KK) ? __float2bfloat16_rn(th / g_S[t]) : __nv_bfloat16(0.f);
}
__global__ void k4bwd() {
    int b = blockIdx.x, t = threadIdx.x;
    float local = 0.f;
    if (t < KK) {
        float cs = 0.f;
        #pragma unroll
        for (int z = 0; z < Z2; z++) cs += g_p2[(size_t)z*BN*KP + (size_t)b*KP + t];
        local = g_ntok[b] * g_tn[(size_t)b*KK + t] / (cs + 1e-30f);
    }
    __shared__ float red[256];
    red[t] = local; __syncthreads();
    for (int s = 128; s > 0; s >>= 1) { if (t < s) red[t] += red[t+s]; __syncthreads(); }
    if (t == 0) g_pB[b] = red[0];
}
__global__ void k_final(float* __restrict__ out) {
    int t = threadIdx.x;
    __shared__ double red[256];
    double s = 0.0;
    for (int i = t; i < NP2; i += 256) s += (double)g_pF[i];
    red[t] = s; __syncthreads();
    for (int st = 128; st > 0; st >>= 1) { if (t < st) red[t] += red[t+st]; __syncthreads(); }
    double fwd = red[0]; __syncthreads();
    s = 0.0;
    for (int i = t; i < NP2; i += 256) s += (double)g_pT[i];
    red[t] = s; __syncthreads();
    for (int st = 128; st > 0; st >>= 1) { if (t < st) red[t] += red[t+st]; __syncthreads(); }
    double tm = red[0]; __syncthreads();
    s = 0.0;
    for (int i = t; i < BN; i += 256) s += (double)g_pB[i];
    red[t] = s; __syncthreads();
    for (int st = 128; st > 0; st >>= 1) { if (t < st) red[t] += red[t+st]; __syncthreads(); }
    double bwd = red[0];
    if (t == 0) {
        out[0] = (float)(tm / (double)BN);
        out[1] = (float)(0.5 * fwd);
        out[2] = (float)(0.5 * bwd);
    }
}

// ---------------- launch (three-stream fork/join; k4bwd overlapped with mm34) ----------------
extern "C" void kernel_launch(void* const* d_in, const int* in_sizes, int n_in,
                              void* d_out, int out_size) {
    const float* bows  = (const float*)d_in[0];
    const float* rho   = (const float*)d_in[1];
    const float* alpha = (const float*)d_in[2];
    const float* W1    = (const float*)d_in[3];
    const float* b1    = (const float*)d_in[4];
    const float* W2    = (const float*)d_in[5];
    const float* b2    = (const float*)d_in[6];
    float* out = (float*)d_out;

    static cudaStream_t s1 = nullptr, s2 = nullptr;
    static cudaEvent_t evF, evB, evS, evW, evT, evK;
    if (!s1) {
        cudaStreamCreateWithFlags(&s1, cudaStreamNonBlocking);
        cudaStreamCreateWithFlags(&s2, cudaStreamNonBlocking);
        cudaEventCreateWithFlags(&evF, cudaEventDisableTiming);
        cudaEventCreateWithFlags(&evB, cudaEventDisableTiming);
        cudaEventCreateWithFlags(&evS, cudaEventDisableTiming);
        cudaEventCreateWithFlags(&evW, cudaEventDisableTiming);
        cudaEventCreateWithFlags(&evT, cudaEventDisableTiming);
        cudaEventCreateWithFlags(&evK, cudaEventDisableTiming);
        cudaFuncSetAttribute(mm<0>, cudaFuncAttributeMaxDynamicSharedMemorySize, MMS);
        cudaFuncSetAttribute(mm<1>, cudaFuncAttributeMaxDynamicSharedMemorySize, MMS);
        cudaFuncSetAttribute(mm<2>, cudaFuncAttributeMaxDynamicSharedMemorySize, MMS);
        cudaFuncSetAttribute(mm34, cudaFuncAttributeMaxDynamicSharedMemorySize, 2*STG34);
    }

    // fork
    cudaEventRecord(evF, 0);
    cudaStreamWaitEvent(s1, evF, 0);
    cudaStreamWaitEvent(s2, evF, 0);

    // chain A (s1): rho/alpha convert -> dis GEMM (+S, disT) -> S reduce
    k_cvt_rho<<<(VV*(HP/4) + 255)/256, 256, 0, s1>>>(rho);
    k_cvt_al<<<(KP*(HP/4) + 255)/256, 256, 0, s1>>>(alpha);
    mm<0><<<dim3(MT, 2), 256, MMS, s1>>>();
    k_sr<<<KP, 128, 0, s1>>>();
    cudaEventRecord(evS, s1);

    // chain C (s2): W1 convert
    k_cvt_w1t<<<dim3(VP/64, NH/64), dim3(32, 8), 0, s2>>>(W1);
    cudaEventRecord(evW, s2);

    // chain B (default): bows convert (+ntok)
    k_cvt_bows<<<BN, 256>>>(bows);
    cudaEventRecord(evB, 0);

    // chain A continues: colsum GEMM (needs bows16 + disT16)
    cudaStreamWaitEvent(s1, evB, 0);
    mm<2><<<dim3(4, 2, Z2), 256, MMS, s1>>>();

    // chain B: hid GEMM -> reduce -> mlp2 -> soft2 (needs g_S)
    cudaStreamWaitEvent(0, evW, 0);
    mm<1><<<dim3(4, 7, Z1), 256, MMS>>>();
    k1_reduce<<<(BN*HIDD + 255)/256, 256>>>(b1);
    k_mlp2<<<dim3(4, 8), 256>>>(W2, b2);
    cudaStreamWaitEvent(0, evS, 0);
    k_soft2<<<BN, 256>>>();
    cudaEventRecord(evT, 0);

    // k4bwd on s1 (needs p2 from mm<2> [same stream] + g_tn from soft2), overlaps mm34
    cudaStreamWaitEvent(s1, evT, 0);
    k4bwd<<<BN, 256, 0, s1>>>();
    cudaEventRecord(evK, s1);

    // merged den+recon on default (needs tn16/th216/dis16)
    mm34<<<dim3(4, NT64), 256, 2*STG34>>>();

    // final: needs pF/pT (default) + pB (s1)
    cudaStreamWaitEvent(0, evK, 0);
    k_final<<<1, 256>>>(out);
}